// round 13
// baseline (speedup 1.0000x reference)
#include <cuda_runtime.h>

#define BB    2048
#define TR    2080   // row length of transposed qx (floats); rows zero-padded
#define TROUT 2048   // row length of transposed output

__device__ float g_qxT[(size_t)BB * TR];
__device__ float g_outT[(size_t)BB * TROUT];   // raw tanh values

// ---------------------------------------------------------------------------
// Kernel A: FIR pre-pass (unchanged from round 8)
// ---------------------------------------------------------------------------
__global__ void __launch_bounds__(128) fir_kernel(
    const float* __restrict__ cur,
    const float* __restrict__ a,
    const float* __restrict__ b_act,
    const float* __restrict__ max_cur,
    int T)
{
    __shared__ float sm[191][64];
    const int li = threadIdx.x & 63;
    const int th = threadIdx.x >> 6;
    const int i  = blockIdx.x * 64 + li;
    const int t0 = blockIdx.y * 128;

    float areg[64];
#pragma unroll
    for (int k = 0; k < 64; ++k) areg[k] = __ldg(&a[k]);
    const float bact   = __ldg(&b_act[0]);
    const float inv_mc = 1.0f / __ldg(&max_cur[0]);

#pragma unroll 4
    for (int rr = th; rr < 191; rr += 2) {
        int s = t0 - 63 + rr;
        sm[rr][li] = (s >= 0 && s < T) ? __ldg(&cur[(size_t)s * BB + i]) : 0.0f;
    }
    __syncthreads();

    float* myrow = g_qxT + (size_t)i * TR;
    const int tb = th * 64;

#pragma unroll 1
    for (int g = 0; g < 8; ++g) {
        const int tt = tb + g * 8;
        float acc[8];
#pragma unroll
        for (int o = 0; o < 8; ++o) acc[o] = 0.0f;
#pragma unroll
        for (int rr = 0; rr < 71; ++rr) {
            float v = sm[tt + rr][li];
#pragma unroll
            for (int o = 0; o < 8; ++o)
                if (rr >= o && rr <= o + 63)
                    acc[o] = fmaf(areg[rr - o], v, acc[o]);
        }
        const int t = t0 + tt;
        float r0 = (acc[0] - bact) * inv_mc, r1 = (acc[1] - bact) * inv_mc;
        float r2 = (acc[2] - bact) * inv_mc, r3 = (acc[3] - bact) * inv_mc;
        float r4 = (acc[4] - bact) * inv_mc, r5 = (acc[5] - bact) * inv_mc;
        float r6 = (acc[6] - bact) * inv_mc, r7 = (acc[7] - bact) * inv_mc;
        if (t + 7 < T) {
            *(float4*)(myrow + t)     = make_float4(r0, r1, r2, r3);
            *(float4*)(myrow + t + 4) = make_float4(r4, r5, r6, r7);
        } else {
            if (t + 0 < T) myrow[t + 0] = r0;
            if (t + 1 < T) myrow[t + 1] = r1;
            if (t + 2 < T) myrow[t + 2] = r2;
            if (t + 3 < T) myrow[t + 3] = r3;
            if (t + 4 < T) myrow[t + 4] = r4;
            if (t + 5 < T) myrow[t + 5] = r5;
            if (t + 6 < T) myrow[t + 6] = r6;
            if (t + 7 < T) myrow[t + 7] = r7;
        }
    }
}

// ---------------------------------------------------------------------------
// Kernel B: 8 lanes/element, rotated taps j = 8r+3..8r+10 (weights 0 for
// j>64), taps 1,2 local to lane0; R11 schedule, but cross-lane traffic via
// volatile smem mailboxes instead of SHFL:
//   broadcast: each lane STS th to its own slot; LDS lane0's slot next step
//   hand-off:  lane r STS valRel to slot r-1; LDS own slot r next step
// Warp-synchronous (same-warp program order), no barriers. Arithmetic
// identical to round 11; raw th stored, mfr applied in tr_kernel.
// ---------------------------------------------------------------------------
#define STEP(p, qv2) { \
    float tbP_ = vB[rdB];                 /* th(s-1) broadcast (from smem) */ \
    float hv_  = vH[rdH];                 /* hand-off value from step s-1 */ \
    /* serial chain */ \
    float xx_ = fmaf(W1L, thPrev, yq[(p)&1]); \
    float u_  = xx_ * xx_; \
    float s1_ = fmaf(c1, xx_, c0); \
    float s2_ = fmaf(c3, xx_, c2); \
    float pv_ = fmaf(u_, s2_, s1_); \
    float pr_ = fmaxf(pv_, 0.0f); \
    float th_; asm("tanh.approx.f32 %0, %1;" : "=f"(th_) : "f"(pr_)); \
    fbv[(p)&7] = th_; \
    vB[myB] = th_;                        /* publish th for next step */ \
    /* deferred seed for slot released LAST step */ \
    R[((p)+7)&7] = hv_ * u7; \
    /* scatter with last step's broadcast */ \
    R[((p)+0)&7] = fmaf(W[0], tbP_, R[((p)+0)&7]); \
    R[((p)+1)&7] = fmaf(W[1], tbP_, R[((p)+1)&7]); \
    R[((p)+2)&7] = fmaf(W[2], tbP_, R[((p)+2)&7]); \
    R[((p)+3)&7] = fmaf(W[3], tbP_, R[((p)+3)&7]); \
    R[((p)+4)&7] = fmaf(W[4], tbP_, R[((p)+4)&7]); \
    R[((p)+5)&7] = fmaf(W[5], tbP_, R[((p)+5)&7]); \
    R[((p)+6)&7] = fmaf(W[6], tbP_, R[((p)+6)&7]); \
    R[((p)+7)&7] = fmaf(W[7], tbP_, R[((p)+7)&7]); \
    /* release + publish hand-off + y/yq update */ \
    float valRel_ = R[(p)&7]; \
    vH[wrH] = valRel_; \
    float y_  = fmaf(W2L, th_, valRel_); \
    yq[(p)&1] = y_ + (qv2); \
    thPrev = th_; \
}

#define S8(qa, qb, nx) \
    STEP(0,(qa).z) STEP(1,(qa).w) STEP(2,(qb).x) STEP(3,(qb).y) \
    STEP(4,(qb).z) STEP(5,(qb).w) STEP(6,(nx).x) STEP(7,(nx).y)

#define EMIT() if (r == 0) { \
        *(float4*)(optr + 0) = make_float4(fbv[0], fbv[1], fbv[2], fbv[3]); \
        *(float4*)(optr + 4) = make_float4(fbv[4], fbv[5], fbv[6], fbv[7]); \
    } \
    optr += 8;

__global__ void __launch_bounds__(128) rec_kernel(
    const float* __restrict__ b_lag,
    const float* __restrict__ poly_coeff,
    const float* __restrict__ max_cur,
    const float* __restrict__ max_fr,
    int T)
{
    __shared__ float Bsh[128], Hsh[128];
    volatile float* vB = Bsh;
    volatile float* vH = Hsh;

    const int tid = threadIdx.x;
    const int r   = tid & 7;
    const int e   = blockIdx.x * 16 + (tid >> 3);

    const int gb  = (tid >> 3) * 8;     // group base in mailbox arrays
    const int myB = gb + r;             // own broadcast slot
    const int rdB = gb;                 // read lane0's slot
    const int wrH = gb + ((r + 7) & 7); // hand-off to lane r-1 (lane0 -> slot7)
    const int rdH = gb + r;             // read own hand-off slot

    Bsh[tid] = 0.0f;
    Hsh[tid] = 0.0f;
    __syncthreads();

    const float inv_mc = 1.0f / __ldg(&max_cur[0]);
    const float mfr    = __ldg(&max_fr[0]);
    float c0 = __ldg(&poly_coeff[0]); c0 *= c0;
    float c1 = __ldg(&poly_coeff[1]); c1 *= c1;
    float c2 = __ldg(&poly_coeff[2]); c2 *= c2;
    float c3 = __ldg(&poly_coeff[3]); c3 *= c3;
    const float cwm = 1000.0f * inv_mc * mfr;   // weights absorb mfr (we scatter th)

    // lane r owns taps j = 8r+3+k (k=0..7); W[k] = cwm*b_lag[64-j], 0 if j>64
    float W[8];
#pragma unroll
    for (int k = 0; k < 8; ++k) {
        int j = 8 * r + 3 + k;
        W[k] = (j <= 64) ? cwm * __ldg(&b_lag[64 - j]) : 0.0f;
    }
    const float W1L = (r == 0) ? cwm * __ldg(&b_lag[63]) : 0.0f;
    const float W2L = (r == 0) ? cwm * __ldg(&b_lag[62]) : 0.0f;
    const float u7  = (r == 7) ? 0.0f : 1.0f;

    float R[8];
#pragma unroll
    for (int k = 0; k < 8; ++k) R[k] = 0.0f;
    float fbv[8];
    float thPrev = 0.0f;

    const float4* qrow = (const float4*)(g_qxT + (size_t)e * TR);
    float* optr = g_outT + (size_t)e * TROUT;

    float4 qa = __ldg(qrow + 0), qb = __ldg(qrow + 1);
    float yq[2] = { qa.x, qa.y };   // y=0 initially, q pre-added

    const int nfull = T >> 3;
    const int npair = nfull >> 1;
    for (int m = 0; m < npair; ++m) {
        float4 na = __ldg(qrow + (size_t)(4 * m) + 2);
        float4 nb = __ldg(qrow + (size_t)(4 * m) + 3);
        S8(qa, qb, na)
        EMIT()
        qa = __ldg(qrow + (size_t)(4 * m) + 4);
        qb = __ldg(qrow + (size_t)(4 * m) + 5);
        S8(na, nb, qa)
        EMIT()
    }
    if (nfull & 1) {
        float4 nq = __ldg(qrow + (size_t)(2 * nfull));   // zero-padded, safe
        S8(qa, qb, nq)
        EMIT()
    }

    // ---- generic tail (T mod 8 steps; empty for T=2000) ----
    const int t0tail = nfull * 8;
    const int tail   = T - t0tail;
    if (tail > 0) {
#pragma unroll 1
        for (int tt = 0; tt < tail; ++tt) {
            int t = t0tail + tt;
            int p = t & 7;
            float tbP = vB[rdB];
            float hv  = vH[rdH];
            float xx = fmaf(W1L, thPrev, yq[p & 1]);
            float u_  = xx * xx;
            float s1_ = fmaf(c1, xx, c0);
            float s2_ = fmaf(c3, xx, c2);
            float pv  = fmaf(u_, s2_, s1_);
            float pr  = fmaxf(pv, 0.0f);
            float th; asm("tanh.approx.f32 %0, %1;" : "=f"(th) : "f"(pr));
            if (r == 0) g_outT[(size_t)e * TROUT + t] = th;
            vB[myB] = th;
            R[(p + 7) & 7] = hv * u7;
#pragma unroll 1
            for (int k = 0; k < 8; ++k)
                R[(p + k) & 7] = fmaf(W[k], tbP, R[(p + k) & 7]);
            float valRel = R[p];
            vH[wrH] = valRel;
            float y_ = fmaf(W2L, th, valRel);
            yq[p & 1] = y_ + __ldg(g_qxT + (size_t)e * TR + (t + 2)); // padded
            thPrev = th;
        }
    }
}

// ---------------------------------------------------------------------------
// Kernel C: transpose g_outT[e][t] -> out[t][e], scaling by mfr.
// ---------------------------------------------------------------------------
__global__ void __launch_bounds__(256) tr_kernel(
    float* __restrict__ out, const float* __restrict__ max_fr, int T)
{
    __shared__ float tile[32][33];
    const int tx = threadIdx.x, ty = threadIdx.y;
    const int e0 = blockIdx.x * 32;
    const int t0 = blockIdx.y * 32;
    const float mfr = __ldg(&max_fr[0]);

#pragma unroll
    for (int j = 0; j < 4; ++j) {
        int e = e0 + ty + 8 * j;
        int t = t0 + tx;
        tile[ty + 8 * j][tx] = (t < T) ? mfr * g_outT[(size_t)e * TROUT + t] : 0.0f;
    }
    __syncthreads();
#pragma unroll
    for (int j = 0; j < 4; ++j) {
        int t = t0 + ty + 8 * j;
        if (t < T) out[(size_t)t * BB + e0 + tx] = tile[tx][ty + 8 * j];
    }
}

// ---------------------------------------------------------------------------
extern "C" void kernel_launch(void* const* d_in, const int* in_sizes, int n_in,
                              void* d_out, int out_size)
{
    const float* currents = (const float*)d_in[0];
    const float* a        = (const float*)d_in[1];
    const float* b_lag    = (const float*)d_in[2];
    const float* poly     = (const float*)d_in[3];
    const float* b_act    = (const float*)d_in[4];
    const float* max_cur  = (const float*)d_in[5];
    const float* max_fr   = (const float*)d_in[6];
    float* out = (float*)d_out;

    const int T = in_sizes[0] / BB;   // 2000

    dim3 gA(BB / 64, (T + 127) / 128);
    fir_kernel<<<gA, 128>>>(currents, a, b_act, max_cur, T);

    rec_kernel<<<BB / 16, 128>>>(b_lag, poly, max_cur, max_fr, T);

    dim3 gC(BB / 32, (T + 31) / 32);
    tr_kernel<<<gC, dim3(32, 8)>>>(out, max_fr, T);
}

// round 14
// speedup vs baseline: 1.2824x; 1.2824x over previous
#include <cuda_runtime.h>

#define BB    2048
#define TR    2080   // row length of transposed qx (floats); rows zero-padded
#define TROUT 2048   // row length of transposed output

__device__ float g_qxT[(size_t)BB * TR];
__device__ float g_outT[(size_t)BB * TROUT];   // raw tanh values

// ---------------------------------------------------------------------------
// Kernel A: FIR pre-pass (unchanged from round 8)
// ---------------------------------------------------------------------------
__global__ void __launch_bounds__(128) fir_kernel(
    const float* __restrict__ cur,
    const float* __restrict__ a,
    const float* __restrict__ b_act,
    const float* __restrict__ max_cur,
    int T)
{
    __shared__ float sm[191][64];
    const int li = threadIdx.x & 63;
    const int th = threadIdx.x >> 6;
    const int i  = blockIdx.x * 64 + li;
    const int t0 = blockIdx.y * 128;

    float areg[64];
#pragma unroll
    for (int k = 0; k < 64; ++k) areg[k] = __ldg(&a[k]);
    const float bact   = __ldg(&b_act[0]);
    const float inv_mc = 1.0f / __ldg(&max_cur[0]);

#pragma unroll 4
    for (int rr = th; rr < 191; rr += 2) {
        int s = t0 - 63 + rr;
        sm[rr][li] = (s >= 0 && s < T) ? __ldg(&cur[(size_t)s * BB + i]) : 0.0f;
    }
    __syncthreads();

    float* myrow = g_qxT + (size_t)i * TR;
    const int tb = th * 64;

#pragma unroll 1
    for (int g = 0; g < 8; ++g) {
        const int tt = tb + g * 8;
        float acc[8];
#pragma unroll
        for (int o = 0; o < 8; ++o) acc[o] = 0.0f;
#pragma unroll
        for (int rr = 0; rr < 71; ++rr) {
            float v = sm[tt + rr][li];
#pragma unroll
            for (int o = 0; o < 8; ++o)
                if (rr >= o && rr <= o + 63)
                    acc[o] = fmaf(areg[rr - o], v, acc[o]);
        }
        const int t = t0 + tt;
        float r0 = (acc[0] - bact) * inv_mc, r1 = (acc[1] - bact) * inv_mc;
        float r2 = (acc[2] - bact) * inv_mc, r3 = (acc[3] - bact) * inv_mc;
        float r4 = (acc[4] - bact) * inv_mc, r5 = (acc[5] - bact) * inv_mc;
        float r6 = (acc[6] - bact) * inv_mc, r7 = (acc[7] - bact) * inv_mc;
        if (t + 7 < T) {
            *(float4*)(myrow + t)     = make_float4(r0, r1, r2, r3);
            *(float4*)(myrow + t + 4) = make_float4(r4, r5, r6, r7);
        } else {
            if (t + 0 < T) myrow[t + 0] = r0;
            if (t + 1 < T) myrow[t + 1] = r1;
            if (t + 2 < T) myrow[t + 2] = r2;
            if (t + 3 < T) myrow[t + 3] = r3;
            if (t + 4 < T) myrow[t + 4] = r4;
            if (t + 5 < T) myrow[t + 5] = r5;
            if (t + 6 < T) myrow[t + 6] = r6;
            if (t + 7 < T) myrow[t + 7] = r7;
        }
    }
}

// ---------------------------------------------------------------------------
// Kernel B: 16 lanes/element, rotated taps j = 4r+3..4r+6 (weights 0 for
// j>64), taps 1,2 local to lane0. R11 software-pipelined schedule (deferred
// seed via hUPrev, scatter via 1-step-old broadcast tbPrev, yq pre-add).
// 2048 el x 16 lanes = 1024 warps = 2 warps/SMSP: the sibling warp hides
// each warp's chain/shfl latency. Raw th stored; mfr folded into weights
// and applied to output in tr_kernel.
// ---------------------------------------------------------------------------
#define STEP(p, qv2) { \
    /* serial chain */ \
    float xx_ = fmaf(W1L, thPrev, yq[(p)&1]); \
    float u_  = xx_ * xx_; \
    float s1_ = fmaf(c1, xx_, c0); \
    float s2_ = fmaf(c3, xx_, c2); \
    float pv_ = fmaf(u_, s2_, s1_); \
    float pr_ = fmaxf(pv_, 0.0f); \
    float th_; asm("tanh.approx.f32 %0, %1;" : "=f"(th_) : "f"(pr_)); \
    fbv[(p)&7] = th_; \
    float tb_ = __shfl_sync(0xffffffffu, th_, 0, 16); \
    /* deferred seed for slot released LAST step (hand-off from lane r+1) */ \
    R[((p)+3)&3] = hUPrev * u15; \
    /* scatter with 1-step-old broadcast */ \
    R[((p)+0)&3] = fmaf(W[0], tbPrev, R[((p)+0)&3]); \
    R[((p)+1)&3] = fmaf(W[1], tbPrev, R[((p)+1)&3]); \
    R[((p)+2)&3] = fmaf(W[2], tbPrev, R[((p)+2)&3]); \
    R[((p)+3)&3] = fmaf(W[3], tbPrev, R[((p)+3)&3]); \
    /* release + next hand-off + y/yq update */ \
    float valRel_ = R[(p)&3]; \
    float hU_ = __shfl_down_sync(0xffffffffu, valRel_, 1, 16); \
    float y_  = fmaf(W2L, th_, valRel_); \
    yq[(p)&1] = y_ + (qv2); \
    thPrev = th_; \
    tbPrev = tb_; \
    hUPrev = hU_; \
}

#define S8(qa, qb, nx) \
    STEP(0,(qa).z) STEP(1,(qa).w) STEP(2,(qb).x) STEP(3,(qb).y) \
    STEP(4,(qb).z) STEP(5,(qb).w) STEP(6,(nx).x) STEP(7,(nx).y)

#define EMIT() if (r == 0) { \
        *(float4*)(optr + 0) = make_float4(fbv[0], fbv[1], fbv[2], fbv[3]); \
        *(float4*)(optr + 4) = make_float4(fbv[4], fbv[5], fbv[6], fbv[7]); \
    } \
    optr += 8;

__global__ void __launch_bounds__(256) rec_kernel(
    const float* __restrict__ b_lag,
    const float* __restrict__ poly_coeff,
    const float* __restrict__ max_cur,
    const float* __restrict__ max_fr,
    int T)
{
    const int tid = threadIdx.x;
    const int r   = tid & 15;                       // lane within 16-lane group
    const int e   = blockIdx.x * 16 + (tid >> 4);   // element index

    const float inv_mc = 1.0f / __ldg(&max_cur[0]);
    const float mfr    = __ldg(&max_fr[0]);
    float c0 = __ldg(&poly_coeff[0]); c0 *= c0;
    float c1 = __ldg(&poly_coeff[1]); c1 *= c1;
    float c2 = __ldg(&poly_coeff[2]); c2 *= c2;
    float c3 = __ldg(&poly_coeff[3]); c3 *= c3;
    const float cwm = 1000.0f * inv_mc * mfr;       // weights absorb mfr

    // lane r owns taps j = 4r+3+k (k=0..3); W[k] = cwm*b_lag[64-j], 0 if j>64
    float W[4];
#pragma unroll
    for (int k = 0; k < 4; ++k) {
        int j = 4 * r + 3 + k;
        W[k] = (j <= 64) ? cwm * __ldg(&b_lag[64 - j]) : 0.0f;
    }
    // lane0-only local taps 1, 2
    const float W1L = (r == 0)  ? cwm * __ldg(&b_lag[63]) : 0.0f;
    const float W2L = (r == 0)  ? cwm * __ldg(&b_lag[62]) : 0.0f;
    const float u15 = (r == 15) ? 0.0f : 1.0f;      // hand-off mask

    float R[4];
#pragma unroll
    for (int k = 0; k < 4; ++k) R[k] = 0.0f;
    float fbv[8];
    float thPrev = 0.0f, tbPrev = 0.0f, hUPrev = 0.0f;

    const float4* qrow = (const float4*)(g_qxT + (size_t)e * TR);
    float* optr = g_outT + (size_t)e * TROUT;

    float4 qa = __ldg(qrow + 0), qb = __ldg(qrow + 1);
    float yq[2] = { qa.x, qa.y };   // y=0 initially, q pre-added

    const int nfull = T >> 3;
    const int npair = nfull >> 1;
    for (int m = 0; m < npair; ++m) {
        float4 na = __ldg(qrow + (size_t)(4 * m) + 2);
        float4 nb = __ldg(qrow + (size_t)(4 * m) + 3);
        S8(qa, qb, na)
        EMIT()
        qa = __ldg(qrow + (size_t)(4 * m) + 4);
        qb = __ldg(qrow + (size_t)(4 * m) + 5);
        S8(na, nb, qa)
        EMIT()
    }
    if (nfull & 1) {
        float4 nq = __ldg(qrow + (size_t)(2 * nfull));   // zero-padded, safe
        S8(qa, qb, nq)
        EMIT()
    }

    // ---- generic tail (T mod 8 steps; empty for T=2000) ----
    const int t0tail = nfull * 8;
    const int tail   = T - t0tail;
    if (tail > 0) {
#pragma unroll 1
        for (int tt = 0; tt < tail; ++tt) {
            int t = t0tail + tt;
            int p = t & 3;
            float xx = fmaf(W1L, thPrev, yq[t & 1]);
            float u_  = xx * xx;
            float s1_ = fmaf(c1, xx, c0);
            float s2_ = fmaf(c3, xx, c2);
            float pv  = fmaf(u_, s2_, s1_);
            float pr  = fmaxf(pv, 0.0f);
            float th; asm("tanh.approx.f32 %0, %1;" : "=f"(th) : "f"(pr));
            if (r == 0) g_outT[(size_t)e * TROUT + t] = th;
            float tbn = __shfl_sync(0xffffffffu, th, 0, 16);
            R[(p + 3) & 3] = hUPrev * u15;
#pragma unroll 1
            for (int k = 0; k < 4; ++k)
                R[(p + k) & 3] = fmaf(W[k], tbPrev, R[(p + k) & 3]);
            float valRel = R[p];
            float hU = __shfl_down_sync(0xffffffffu, valRel, 1, 16);
            float y_ = fmaf(W2L, th, valRel);
            yq[t & 1] = y_ + __ldg(g_qxT + (size_t)e * TR + (t + 2)); // padded
            thPrev = th; tbPrev = tbn; hUPrev = hU;
        }
    }
}

// ---------------------------------------------------------------------------
// Kernel C: transpose g_outT[e][t] -> out[t][e], scaling by mfr.
// ---------------------------------------------------------------------------
__global__ void __launch_bounds__(256) tr_kernel(
    float* __restrict__ out, const float* __restrict__ max_fr, int T)
{
    __shared__ float tile[32][33];
    const int tx = threadIdx.x, ty = threadIdx.y;
    const int e0 = blockIdx.x * 32;
    const int t0 = blockIdx.y * 32;
    const float mfr = __ldg(&max_fr[0]);

#pragma unroll
    for (int j = 0; j < 4; ++j) {
        int e = e0 + ty + 8 * j;
        int t = t0 + tx;
        tile[ty + 8 * j][tx] = (t < T) ? mfr * g_outT[(size_t)e * TROUT + t] : 0.0f;
    }
    __syncthreads();
#pragma unroll
    for (int j = 0; j < 4; ++j) {
        int t = t0 + ty + 8 * j;
        if (t < T) out[(size_t)t * BB + e0 + tx] = tile[tx][ty + 8 * j];
    }
}

// ---------------------------------------------------------------------------
extern "C" void kernel_launch(void* const* d_in, const int* in_sizes, int n_in,
                              void* d_out, int out_size)
{
    const float* currents = (const float*)d_in[0];
    const float* a        = (const float*)d_in[1];
    const float* b_lag    = (const float*)d_in[2];
    const float* poly     = (const float*)d_in[3];
    const float* b_act    = (const float*)d_in[4];
    const float* max_cur  = (const float*)d_in[5];
    const float* max_fr   = (const float*)d_in[6];
    float* out = (float*)d_out;

    const int T = in_sizes[0] / BB;   // 2000

    dim3 gA(BB / 64, (T + 127) / 128);
    fir_kernel<<<gA, 128>>>(currents, a, b_act, max_cur, T);

    // 16 lanes/element, 16 elements per 256-thread block -> 128 blocks,
    // 1024 warps -> 2 warps per SMSP chip-wide.
    rec_kernel<<<BB / 16, 256>>>(b_lag, poly, max_cur, max_fr, T);

    dim3 gC(BB / 32, (T + 31) / 32);
    tr_kernel<<<gC, dim3(32, 8)>>>(out, max_fr, T);
}

// round 15
// speedup vs baseline: 1.3009x; 1.0144x over previous
#include <cuda_runtime.h>

#define BB    2048
#define TROUT 2048   // row length of transposed output

__device__ float g_outT[(size_t)BB * TROUT];   // raw tanh values

// ---------------------------------------------------------------------------
// Fused kernel: FIR + recurrence. 16 lanes/element (R14 layout, 2 warps/SMSP).
// Two systolic rings per lane:
//   R[4]  feedback: taps j=4r+3..4r+6 (0 for j>64), scatter input tbPrev=th(s-1)
//   RX[4] FIR:      taps d=4r+3..4r+6 (0 for d>63), scatter input cur(s-1)
// Local on lane0: FB taps 1 (consume patch W1L) & 2 (release W2L);
//   FIR taps d=0,1,2 via prefetched cur(s+2),cur(s+1),cur(s) at release time,
//   chain seeded with xoffC = -b_act/max_cur.
// cur prefetched via 8-deep register ring (1 scalar LDG/step, same-address
// within a 16-lane group -> 1 transaction/warp/step, ~8 steps of slack).
// ---------------------------------------------------------------------------
#define STEP(p, PREF) { \
    float cm1_ = cbuf[((p)+7)&7];          /* cur(s-1) */ \
    PREF \
    /* serial chain */ \
    float xx_ = fmaf(W1L, thPrev, yq[(p)&1]); \
    float u_  = xx_ * xx_; \
    float s1_ = fmaf(c1, xx_, c0); \
    float s2_ = fmaf(c3, xx_, c2); \
    float pv_ = fmaf(u_, s2_, s1_); \
    float pr_ = fmaxf(pv_, 0.0f); \
    float th_; asm("tanh.approx.f32 %0, %1;" : "=f"(th_) : "f"(pr_)); \
    fbv[(p)&7] = th_; \
    float tb_ = __shfl_sync(0xffffffffu, th_, 0, 16); \
    /* feedback ring: deferred seed + scatter with 1-step-old broadcast */ \
    R[((p)+3)&3] = hUPrev * u15; \
    R[((p)+0)&3] = fmaf(W[0], tbPrev, R[((p)+0)&3]); \
    R[((p)+1)&3] = fmaf(W[1], tbPrev, R[((p)+1)&3]); \
    R[((p)+2)&3] = fmaf(W[2], tbPrev, R[((p)+2)&3]); \
    R[((p)+3)&3] = fmaf(W[3], tbPrev, R[((p)+3)&3]); \
    float valRel_ = R[(p)&3]; \
    float hU_ = __shfl_down_sync(0xffffffffu, valRel_, 1, 16); \
    /* FIR ring: same structure, input cur(s-1) (no shfl needed) */ \
    RX[((p)+3)&3] = hXPrev * u15; \
    RX[((p)+0)&3] = fmaf(GX[0], cm1_, RX[((p)+0)&3]); \
    RX[((p)+1)&3] = fmaf(GX[1], cm1_, RX[((p)+1)&3]); \
    RX[((p)+2)&3] = fmaf(GX[2], cm1_, RX[((p)+2)&3]); \
    RX[((p)+3)&3] = fmaf(GX[3], cm1_, RX[((p)+3)&3]); \
    float xRel_ = RX[(p)&3]; \
    float hX_ = __shfl_down_sync(0xffffffffu, xRel_, 1, 16); \
    /* assemble yq for target step s+2 */ \
    float t0_ = fmaf(A0, cbuf[((p)+2)&7], xoffC); \
    float t1_ = fmaf(A1, cbuf[((p)+1)&7], t0_); \
    float t2_ = fmaf(A2, cbuf[((p)+0)&7], t1_); \
    float t3_ = t2_ + xRel_; \
    float t4_ = fmaf(W2L, th_, valRel_); \
    yq[(p)&1] = t3_ + t4_; \
    thPrev = th_; tbPrev = tb_; hUPrev = hU_; hXPrev = hX_; \
}

#define PREF_SAFE(p)  cbuf[((p)+7)&7] = __ldg(cb + (size_t)((p)+7) * BB);
#define PREF_CLAMP(p) { int tl_ = bbase + (p) + 7; if (tl_ > Tm1) tl_ = Tm1; \
                        cbuf[((p)+7)&7] = __ldg(cbase + (size_t)tl_ * BB); }

#define S8S() STEP(0,PREF_SAFE(0)) STEP(1,PREF_SAFE(1)) STEP(2,PREF_SAFE(2)) STEP(3,PREF_SAFE(3)) \
              STEP(4,PREF_SAFE(4)) STEP(5,PREF_SAFE(5)) STEP(6,PREF_SAFE(6)) STEP(7,PREF_SAFE(7))
#define S8C() STEP(0,PREF_CLAMP(0)) STEP(1,PREF_CLAMP(1)) STEP(2,PREF_CLAMP(2)) STEP(3,PREF_CLAMP(3)) \
              STEP(4,PREF_CLAMP(4)) STEP(5,PREF_CLAMP(5)) STEP(6,PREF_CLAMP(6)) STEP(7,PREF_CLAMP(7))

#define EMIT() if (r == 0) { \
        *(float4*)(optr + 0) = make_float4(fbv[0], fbv[1], fbv[2], fbv[3]); \
        *(float4*)(optr + 4) = make_float4(fbv[4], fbv[5], fbv[6], fbv[7]); \
    } \
    optr += 8;

__global__ void __launch_bounds__(256) rec_kernel(
    const float* __restrict__ cur,
    const float* __restrict__ a,
    const float* __restrict__ b_lag,
    const float* __restrict__ poly_coeff,
    const float* __restrict__ b_act,
    const float* __restrict__ max_cur,
    const float* __restrict__ max_fr,
    int T)
{
    const int tid = threadIdx.x;
    const int r   = tid & 15;                       // lane within 16-lane group
    const int e   = blockIdx.x * 16 + (tid >> 4);   // element index

    const float inv_mc = 1.0f / __ldg(&max_cur[0]);
    const float mfr    = __ldg(&max_fr[0]);
    float c0 = __ldg(&poly_coeff[0]); c0 *= c0;
    float c1 = __ldg(&poly_coeff[1]); c1 *= c1;
    float c2 = __ldg(&poly_coeff[2]); c2 *= c2;
    float c3 = __ldg(&poly_coeff[3]); c3 *= c3;
    const float cwm   = 1000.0f * inv_mc * mfr;     // FB weights absorb mfr
    const float xoffC = -__ldg(&b_act[0]) * inv_mc;

    // feedback: lane r owns taps j = 4r+3+k (k=0..3)
    float W[4];
#pragma unroll
    for (int k = 0; k < 4; ++k) {
        int j = 4 * r + 3 + k;
        W[k] = (j <= 64) ? cwm * __ldg(&b_lag[64 - j]) : 0.0f;
    }
    const float W1L = (r == 0)  ? cwm * __ldg(&b_lag[63]) : 0.0f;
    const float W2L = (r == 0)  ? cwm * __ldg(&b_lag[62]) : 0.0f;

    // FIR: g[d] = a[63-d], weights scaled by inv_mc; lane r owns d = 4r+3+k
    float GX[4];
#pragma unroll
    for (int k = 0; k < 4; ++k) {
        int idx = 60 - 4 * r - k;                    // 63 - d
        GX[k] = (idx >= 0) ? inv_mc * __ldg(&a[idx]) : 0.0f;
    }
    const float A0 = (r == 0) ? inv_mc * __ldg(&a[63]) : 0.0f;  // d=0
    const float A1 = (r == 0) ? inv_mc * __ldg(&a[62]) : 0.0f;  // d=1
    const float A2 = (r == 0) ? inv_mc * __ldg(&a[61]) : 0.0f;  // d=2

    const float u15 = (r == 15) ? 0.0f : 1.0f;      // hand-off mask (both rings)

    float R[4], RX[4];
#pragma unroll
    for (int k = 0; k < 4; ++k) { R[k] = 0.0f; RX[k] = 0.0f; }
    float fbv[8];
    float thPrev = 0.0f, tbPrev = 0.0f, hUPrev = 0.0f, hXPrev = 0.0f;

    const float* cbase = cur + e;                   // cur[t][e]
    float* optr = g_outT + (size_t)e * TROUT;
    const int Tm1 = T - 1;

    // cur prefetch ring: slot j holds cur(t), t == j (mod 8); window s-1..s+6
    float cbuf[8];
    cbuf[7] = 0.0f;                                  // cur(-1) = 0
#pragma unroll
    for (int j = 0; j < 7; ++j)
        cbuf[j] = (j <= Tm1) ? __ldg(cbase + (size_t)j * BB) : 0.0f;

    // yq init: x(0), x(1) local-tap-only (history is zero)
    float yq[2];
    yq[0] = fmaf(A0, cbuf[0], xoffC);
    yq[1] = fmaf(A0, cbuf[1], fmaf(A1, cbuf[0], xoffC));

    const int nfull = T >> 3;
    int nsafe = (T >= 15) ? ((T - 15) / 8 + 1) : 0;  // blocks with in-bounds s+7
    if (nsafe > nfull) nsafe = nfull;

    int b = 0;
    for (; b < nsafe; ++b) {
        const float* cb = cbase + (size_t)(8 * b) * BB;
        S8S()
        EMIT()
    }
    for (; b < nfull; ++b) {
        const int bbase = 8 * b;
        S8C()
        EMIT()
    }

    // ---- generic tail (T mod 8 steps; empty for T=2000) ----
    const int t0tail = nfull * 8;
    const int tail   = T - t0tail;
    if (tail > 0) {
        float Rd[4], RXd[4], cb2[8];
#pragma unroll
        for (int k = 0; k < 4; ++k) { Rd[k] = R[k]; RXd[k] = RX[k]; }
#pragma unroll
        for (int k = 0; k < 8; ++k) cb2[k] = cbuf[k];
#pragma unroll 1
        for (int tt = 0; tt < tail; ++tt) {
            int t = t0tail + tt;
            int p = t & 3;
            int pc = t & 7;
            float cm1 = cb2[(pc + 7) & 7];
            int tl = t + 7; if (tl > Tm1) tl = Tm1;
            cb2[(pc + 7) & 7] = __ldg(cbase + (size_t)tl * BB);
            float xx = fmaf(W1L, thPrev, yq[t & 1]);
            float u_  = xx * xx;
            float s1_ = fmaf(c1, xx, c0);
            float s2_ = fmaf(c3, xx, c2);
            float pv  = fmaf(u_, s2_, s1_);
            float pr  = fmaxf(pv, 0.0f);
            float th; asm("tanh.approx.f32 %0, %1;" : "=f"(th) : "f"(pr));
            if (r == 0) g_outT[(size_t)e * TROUT + t] = th;
            float tbn = __shfl_sync(0xffffffffu, th, 0, 16);
            Rd[(p + 3) & 3] = hUPrev * u15;
#pragma unroll 1
            for (int k = 0; k < 4; ++k)
                Rd[(p + k) & 3] = fmaf(W[k], tbPrev, Rd[(p + k) & 3]);
            float valRel = Rd[p];
            float hU = __shfl_down_sync(0xffffffffu, valRel, 1, 16);
            RXd[(p + 3) & 3] = hXPrev * u15;
#pragma unroll 1
            for (int k = 0; k < 4; ++k)
                RXd[(p + k) & 3] = fmaf(GX[k], cm1, RXd[(p + k) & 3]);
            float xRel = RXd[p];
            float hX = __shfl_down_sync(0xffffffffu, xRel, 1, 16);
            float t0 = fmaf(A0, cb2[(pc + 2) & 7], xoffC);
            float t1 = fmaf(A1, cb2[(pc + 1) & 7], t0);
            float t2 = fmaf(A2, cb2[(pc + 0) & 7], t1);
            float t3 = t2 + xRel;
            float t4 = fmaf(W2L, th, valRel);
            yq[t & 1] = t3 + t4;
            thPrev = th; tbPrev = tbn; hUPrev = hU; hXPrev = hX;
        }
    }
}

// ---------------------------------------------------------------------------
// Kernel C: transpose g_outT[e][t] -> out[t][e], scaling by mfr.
// ---------------------------------------------------------------------------
__global__ void __launch_bounds__(256) tr_kernel(
    float* __restrict__ out, const float* __restrict__ max_fr, int T)
{
    __shared__ float tile[32][33];
    const int tx = threadIdx.x, ty = threadIdx.y;
    const int e0 = blockIdx.x * 32;
    const int t0 = blockIdx.y * 32;
    const float mfr = __ldg(&max_fr[0]);

#pragma unroll
    for (int j = 0; j < 4; ++j) {
        int e = e0 + ty + 8 * j;
        int t = t0 + tx;
        tile[ty + 8 * j][tx] = (t < T) ? mfr * g_outT[(size_t)e * TROUT + t] : 0.0f;
    }
    __syncthreads();
#pragma unroll
    for (int j = 0; j < 4; ++j) {
        int t = t0 + ty + 8 * j;
        if (t < T) out[(size_t)t * BB + e0 + tx] = tile[tx][ty + 8 * j];
    }
}

// ---------------------------------------------------------------------------
extern "C" void kernel_launch(void* const* d_in, const int* in_sizes, int n_in,
                              void* d_out, int out_size)
{
    const float* currents = (const float*)d_in[0];
    const float* a        = (const float*)d_in[1];
    const float* b_lag    = (const float*)d_in[2];
    const float* poly     = (const float*)d_in[3];
    const float* b_act    = (const float*)d_in[4];
    const float* max_cur  = (const float*)d_in[5];
    const float* max_fr   = (const float*)d_in[6];
    float* out = (float*)d_out;

    const int T = in_sizes[0] / BB;   // 2000

    // fused FIR + recurrence: 16 lanes/element, 16 elements per 256-thread
    // block -> 128 blocks, 1024 warps -> 2 warps per SMSP chip-wide.
    rec_kernel<<<BB / 16, 256>>>(currents, a, b_lag, poly, b_act,
                                 max_cur, max_fr, T);

    dim3 gC(BB / 32, (T + 31) / 32);
    tr_kernel<<<gC, dim3(32, 8)>>>(out, max_fr, T);
}

// round 16
// speedup vs baseline: 1.4821x; 1.1393x over previous
#include <cuda_runtime.h>

#define BB    2048
#define TROUT 2048   // row length of transposed output

__device__ float g_outT[(size_t)BB * TROUT];   // raw tanh values

// ---------------------------------------------------------------------------
// Fused FIR + recurrence. 16 lanes/element, 2 warps/SMSP (R15), but cur is
// PAIR-BATCHED: 16 clamped LDGs issued at the top of each 16-step pair for
// the NEXT pair (consumed ~1200 cyc later, 1-2 SB slots, no aliasing).
// STEP takes its cur window values as explicit registers - zero memory ops
// in the step body.
// Rings (per lane):
//   R[4]  feedback: taps j=4r+3..4r+6 (0 for j>64), scatter input tbPrev
//   RX[4] FIR:      taps d=4r+3..4r+6 (0 for d>63), scatter input cur(s-1)
// Lane0 local: FB taps 1 (W1L consume-patch), 2 (W2L release);
//   FIR taps d=0,1,2 from cur(s+2),cur(s+1),cur(s); chain seed xoffC.
// ---------------------------------------------------------------------------
#define STEP(p, cm1, cc0, cc1, cc2) { \
    /* serial chain */ \
    float xx_ = fmaf(W1L, thPrev, yq[(p)&1]); \
    float u_  = xx_ * xx_; \
    float s1_ = fmaf(c1, xx_, c0); \
    float s2_ = fmaf(c3, xx_, c2); \
    float pv_ = fmaf(u_, s2_, s1_); \
    float pr_ = fmaxf(pv_, 0.0f); \
    float th_; asm("tanh.approx.f32 %0, %1;" : "=f"(th_) : "f"(pr_)); \
    fbv[(p)&7] = th_; \
    float tb_ = __shfl_sync(0xffffffffu, th_, 0, 16); \
    /* feedback ring: deferred seed + scatter with 1-step-old broadcast */ \
    R[((p)+3)&3] = hUPrev * u15; \
    R[((p)+0)&3] = fmaf(W[0], tbPrev, R[((p)+0)&3]); \
    R[((p)+1)&3] = fmaf(W[1], tbPrev, R[((p)+1)&3]); \
    R[((p)+2)&3] = fmaf(W[2], tbPrev, R[((p)+2)&3]); \
    R[((p)+3)&3] = fmaf(W[3], tbPrev, R[((p)+3)&3]); \
    float valRel_ = R[(p)&3]; \
    float hU_ = __shfl_down_sync(0xffffffffu, valRel_, 1, 16); \
    /* FIR ring: input cur(s-1), no shfl needed */ \
    RX[((p)+3)&3] = hXPrev * u15; \
    RX[((p)+0)&3] = fmaf(GX[0], (cm1), RX[((p)+0)&3]); \
    RX[((p)+1)&3] = fmaf(GX[1], (cm1), RX[((p)+1)&3]); \
    RX[((p)+2)&3] = fmaf(GX[2], (cm1), RX[((p)+2)&3]); \
    RX[((p)+3)&3] = fmaf(GX[3], (cm1), RX[((p)+3)&3]); \
    float xRel_ = RX[(p)&3]; \
    float hX_ = __shfl_down_sync(0xffffffffu, xRel_, 1, 16); \
    /* assemble yq for target step s+2 */ \
    float t0_ = fmaf(A0, (cc2), xoffC); \
    float t1_ = fmaf(A1, (cc1), t0_); \
    float t2_ = fmaf(A2, (cc0), t1_); \
    float t3_ = t2_ + xRel_; \
    float t4_ = fmaf(W2L, th_, valRel_); \
    yq[(p)&1] = t3_ + t4_; \
    thPrev = th_; tbPrev = tb_; hUPrev = hU_; hXPrev = hX_; \
}

// even block of a pair: steps use window cprev, ca[0..7], cb[0..1]
#define S8E() \
    STEP(0, cprev, ca[0], ca[1], ca[2]) \
    STEP(1, ca[0], ca[1], ca[2], ca[3]) \
    STEP(2, ca[1], ca[2], ca[3], ca[4]) \
    STEP(3, ca[2], ca[3], ca[4], ca[5]) \
    STEP(4, ca[3], ca[4], ca[5], ca[6]) \
    STEP(5, ca[4], ca[5], ca[6], ca[7]) \
    STEP(6, ca[5], ca[6], ca[7], cb[0]) \
    STEP(7, ca[6], ca[7], cb[0], cb[1])

// odd block: window ca[7], cb[0..7], na[0..1]
#define S8O() \
    STEP(0, ca[7], cb[0], cb[1], cb[2]) \
    STEP(1, cb[0], cb[1], cb[2], cb[3]) \
    STEP(2, cb[1], cb[2], cb[3], cb[4]) \
    STEP(3, cb[2], cb[3], cb[4], cb[5]) \
    STEP(4, cb[3], cb[4], cb[5], cb[6]) \
    STEP(5, cb[4], cb[5], cb[6], cb[7]) \
    STEP(6, cb[5], cb[6], cb[7], na[0]) \
    STEP(7, cb[6], cb[7], na[0], na[1])

#define EMIT() if (r == 0) { \
        *(float4*)(optr + 0) = make_float4(fbv[0], fbv[1], fbv[2], fbv[3]); \
        *(float4*)(optr + 4) = make_float4(fbv[4], fbv[5], fbv[6], fbv[7]); \
    } \
    optr += 8;

__global__ void __launch_bounds__(256) rec_kernel(
    const float* __restrict__ cur,
    const float* __restrict__ a,
    const float* __restrict__ b_lag,
    const float* __restrict__ poly_coeff,
    const float* __restrict__ b_act,
    const float* __restrict__ max_cur,
    const float* __restrict__ max_fr,
    int T)
{
    const int tid = threadIdx.x;
    const int r   = tid & 15;                       // lane within 16-lane group
    const int e   = blockIdx.x * 16 + (tid >> 4);   // element index

    const float inv_mc = 1.0f / __ldg(&max_cur[0]);
    const float mfr    = __ldg(&max_fr[0]);
    float c0 = __ldg(&poly_coeff[0]); c0 *= c0;
    float c1 = __ldg(&poly_coeff[1]); c1 *= c1;
    float c2 = __ldg(&poly_coeff[2]); c2 *= c2;
    float c3 = __ldg(&poly_coeff[3]); c3 *= c3;
    const float cwm   = 1000.0f * inv_mc * mfr;     // FB weights absorb mfr
    const float xoffC = -__ldg(&b_act[0]) * inv_mc;

    // feedback: lane r owns taps j = 4r+3+k (k=0..3)
    float W[4];
#pragma unroll
    for (int k = 0; k < 4; ++k) {
        int j = 4 * r + 3 + k;
        W[k] = (j <= 64) ? cwm * __ldg(&b_lag[64 - j]) : 0.0f;
    }
    const float W1L = (r == 0)  ? cwm * __ldg(&b_lag[63]) : 0.0f;
    const float W2L = (r == 0)  ? cwm * __ldg(&b_lag[62]) : 0.0f;

    // FIR: lane r owns lags d = 4r+3+k; weight inv_mc * a[63-d]
    float GX[4];
#pragma unroll
    for (int k = 0; k < 4; ++k) {
        int idx = 60 - 4 * r - k;                    // 63 - d
        GX[k] = (idx >= 0) ? inv_mc * __ldg(&a[idx]) : 0.0f;
    }
    const float A0 = (r == 0) ? inv_mc * __ldg(&a[63]) : 0.0f;  // d=0
    const float A1 = (r == 0) ? inv_mc * __ldg(&a[62]) : 0.0f;  // d=1
    const float A2 = (r == 0) ? inv_mc * __ldg(&a[61]) : 0.0f;  // d=2

    const float u15 = (r == 15) ? 0.0f : 1.0f;

    float R[4], RX[4];
#pragma unroll
    for (int k = 0; k < 4; ++k) { R[k] = 0.0f; RX[k] = 0.0f; }
    float fbv[8];
    float thPrev = 0.0f, tbPrev = 0.0f, hUPrev = 0.0f, hXPrev = 0.0f;

    const float* cbase = cur + e;                   // cur[t][e]
    float* optr = g_outT + (size_t)e * TROUT;
    const int Tm1 = T - 1;

    // initial window: cprev = cur(-1) = 0; ca = cur(0..7), cb = cur(8..15)
    float cprev = 0.0f;
    float ca[8], cb[8], na[8], nb[8];
#pragma unroll
    for (int j = 0; j < 8; ++j) {
        int t0c = (j      <= Tm1) ? j      : Tm1;
        int t1c = (j + 8  <= Tm1) ? j + 8  : Tm1;
        ca[j] = __ldg(cbase + (size_t)t0c * BB);
        cb[j] = __ldg(cbase + (size_t)t1c * BB);
    }

    // yq init: x(0), x(1) from local taps only (all history zero)
    float yq[2];
    yq[0] = fmaf(A0, ca[0], xoffC);
    yq[1] = fmaf(A0, ca[1], fmaf(A1, ca[0], xoffC));

    const int npair = T >> 4;                        // full 16-step pairs
    for (int m = 0; m < npair; ++m) {
        // batched prefetch for pair m+1 (clamped; consumed 16 steps later)
        const int base = 16 * (m + 1);
#pragma unroll
        for (int j = 0; j < 8; ++j) {
            int ta = base + j;     if (ta > Tm1) ta = Tm1;
            int tb2 = base + 8 + j; if (tb2 > Tm1) tb2 = Tm1;
            na[j] = __ldg(cbase + (size_t)ta * BB);
            nb[j] = __ldg(cbase + (size_t)tb2 * BB);
        }
        S8E()
        EMIT()
        S8O()
        EMIT()
        cprev = cb[7];
#pragma unroll
        for (int j = 0; j < 8; ++j) { ca[j] = na[j]; cb[j] = nb[j]; }
    }

    // ---- generic tail (T mod 16 steps; empty for T=2000) ----
    const int t0tail = npair * 16;
    const int tail   = T - t0tail;
    if (tail > 0) {
        // window copy: ct[k] = cur(t0tail - 1 + k), k = 0..17 (clamped)
        float ct[18];
        ct[0] = cprev;
#pragma unroll
        for (int k = 0; k < 8; ++k) { ct[1 + k] = ca[k]; ct[9 + k] = cb[k]; }
        {
            int tl = t0tail + 16; if (tl > Tm1) tl = Tm1;
            ct[17] = __ldg(cbase + (size_t)tl * BB);
        }
        float Rd[4], RXd[4];
#pragma unroll
        for (int k = 0; k < 4; ++k) { Rd[k] = R[k]; RXd[k] = RX[k]; }
#pragma unroll 1
        for (int tt = 0; tt < tail; ++tt) {
            int t = t0tail + tt;
            int p = t & 3;
            float cm1 = ct[tt];
            float xx = fmaf(W1L, thPrev, yq[t & 1]);
            float u_  = xx * xx;
            float s1_ = fmaf(c1, xx, c0);
            float s2_ = fmaf(c3, xx, c2);
            float pv  = fmaf(u_, s2_, s1_);
            float pr  = fmaxf(pv, 0.0f);
            float th; asm("tanh.approx.f32 %0, %1;" : "=f"(th) : "f"(pr));
            if (r == 0) g_outT[(size_t)e * TROUT + t] = th;
            float tbn = __shfl_sync(0xffffffffu, th, 0, 16);
            Rd[(p + 3) & 3] = hUPrev * u15;
#pragma unroll 1
            for (int k = 0; k < 4; ++k)
                Rd[(p + k) & 3] = fmaf(W[k], tbPrev, Rd[(p + k) & 3]);
            float valRel = Rd[p];
            float hU = __shfl_down_sync(0xffffffffu, valRel, 1, 16);
            RXd[(p + 3) & 3] = hXPrev * u15;
#pragma unroll 1
            for (int k = 0; k < 4; ++k)
                RXd[(p + k) & 3] = fmaf(GX[k], cm1, RXd[(p + k) & 3]);
            float xRel = RXd[p];
            float hX = __shfl_down_sync(0xffffffffu, xRel, 1, 16);
            float t0 = fmaf(A0, ct[tt + 3], xoffC);
            float t1 = fmaf(A1, ct[tt + 2], t0);
            float t2 = fmaf(A2, ct[tt + 1], t1);
            float t3 = t2 + xRel;
            float t4 = fmaf(W2L, th, valRel);
            yq[t & 1] = t3 + t4;
            thPrev = th; tbPrev = tbn; hUPrev = hU; hXPrev = hX;
        }
    }
}

// ---------------------------------------------------------------------------
// Kernel C: transpose g_outT[e][t] -> out[t][e], scaling by mfr.
// ---------------------------------------------------------------------------
__global__ void __launch_bounds__(256) tr_kernel(
    float* __restrict__ out, const float* __restrict__ max_fr, int T)
{
    __shared__ float tile[32][33];
    const int tx = threadIdx.x, ty = threadIdx.y;
    const int e0 = blockIdx.x * 32;
    const int t0 = blockIdx.y * 32;
    const float mfr = __ldg(&max_fr[0]);

#pragma unroll
    for (int j = 0; j < 4; ++j) {
        int e = e0 + ty + 8 * j;
        int t = t0 + tx;
        tile[ty + 8 * j][tx] = (t < T) ? mfr * g_outT[(size_t)e * TROUT + t] : 0.0f;
    }
    __syncthreads();
#pragma unroll
    for (int j = 0; j < 4; ++j) {
        int t = t0 + ty + 8 * j;
        if (t < T) out[(size_t)t * BB + e0 + tx] = tile[tx][ty + 8 * j];
    }
}

// ---------------------------------------------------------------------------
extern "C" void kernel_launch(void* const* d_in, const int* in_sizes, int n_in,
                              void* d_out, int out_size)
{
    const float* currents = (const float*)d_in[0];
    const float* a        = (const float*)d_in[1];
    const float* b_lag    = (const float*)d_in[2];
    const float* poly     = (const float*)d_in[3];
    const float* b_act    = (const float*)d_in[4];
    const float* max_cur  = (const float*)d_in[5];
    const float* max_fr   = (const float*)d_in[6];
    float* out = (float*)d_out;

    const int T = in_sizes[0] / BB;   // 2000

    rec_kernel<<<BB / 16, 256>>>(currents, a, b_lag, poly, b_act,
                                 max_cur, max_fr, T);

    dim3 gC(BB / 32, (T + 31) / 32);
    tr_kernel<<<gC, dim3(32, 8)>>>(out, max_fr, T);
}